// round 1
// baseline (speedup 1.0000x reference)
#include <cuda_runtime.h>
#include <math.h>

// ---------------------------------------------------------------------------
// Problem constants
// ---------------------------------------------------------------------------
#define D_MODEL   1024
#define NUM_HEADS 16
#define HEAD_DIM  64
#define BSZ       2
#define TSEQ      2048
#define MROWS     (BSZ * TSEQ)      // 4096
#define QBLK      128               // block-sparse block size

// ---------------------------------------------------------------------------
// Scratch (device globals: allocation-free per harness rules)
// ---------------------------------------------------------------------------
__device__ float g_Q[(size_t)BSZ * NUM_HEADS * TSEQ * HEAD_DIM];   // [B,H,T,hd]
__device__ float g_K[(size_t)BSZ * NUM_HEADS * TSEQ * HEAD_DIM];
__device__ float g_V[(size_t)BSZ * NUM_HEADS * TSEQ * HEAD_DIM];
__device__ float g_AO[(size_t)MROWS * D_MODEL];                    // [B,T,C]

// ---------------------------------------------------------------------------
// Tiled fp32 GEMM body: C_tile(128x128) = A(4096x1024) * W(1024x1024)
// 256 threads, 8x8 micro-tile per thread, BK=8.
// ---------------------------------------------------------------------------
#define BM 128
#define BN 128
#define BK 8

__device__ __forceinline__ void gemm_tile_body(const float* __restrict__ A,
                                               const float* __restrict__ W,
                                               float acc[8][8])
{
    __shared__ float As[BK][BM];
    __shared__ float Bs[BK][BN];

    const int tid  = threadIdx.x;
    const int m0   = blockIdx.y * BM;
    const int n0   = blockIdx.x * BN;
    const int arow = tid >> 1;           // 0..127
    const int acol = (tid & 1) * 4;      // 0 or 4
    const int brow = tid >> 5;           // 0..7
    const int bcol = (tid & 31) * 4;     // 0..124
    const int tr   = (tid >> 4) * 8;     // 0..120
    const int tc   = (tid & 15) * 8;     // 0..120

    #pragma unroll
    for (int i = 0; i < 8; i++)
        #pragma unroll
        for (int j = 0; j < 8; j++)
            acc[i][j] = 0.0f;

    for (int k0 = 0; k0 < 1024; k0 += BK) {
        // load A tile (transposed into smem: As[k][m])
        float4 av = *(const float4*)(A + (size_t)(m0 + arow) * 1024 + k0 + acol);
        As[acol + 0][arow] = av.x;
        As[acol + 1][arow] = av.y;
        As[acol + 2][arow] = av.z;
        As[acol + 3][arow] = av.w;
        // load W tile (natural layout Bs[k][n])
        *(float4*)&Bs[brow][bcol] =
            *(const float4*)(W + (size_t)(k0 + brow) * 1024 + n0 + bcol);
        __syncthreads();

        #pragma unroll
        for (int kk = 0; kk < BK; kk++) {
            float4 a0 = *(const float4*)&As[kk][tr];
            float4 a1 = *(const float4*)&As[kk][tr + 4];
            float4 b0 = *(const float4*)&Bs[kk][tc];
            float4 b1 = *(const float4*)&Bs[kk][tc + 4];
            float ra[8] = {a0.x, a0.y, a0.z, a0.w, a1.x, a1.y, a1.z, a1.w};
            float rb[8] = {b0.x, b0.y, b0.z, b0.w, b1.x, b1.y, b1.z, b1.w};
            #pragma unroll
            for (int i = 0; i < 8; i++)
                #pragma unroll
                for (int j = 0; j < 8; j++)
                    acc[i][j] = fmaf(ra[i], rb[j], acc[i][j]);
        }
        __syncthreads();
    }
}

// ---------------------------------------------------------------------------
// QKV projection: X @ {Wq,Wk,Wv} + bias -> g_Q/g_K/g_V in [B,H,T,hd] layout.
// grid = (8, 32, 3), block = 256
// ---------------------------------------------------------------------------
__global__ __launch_bounds__(256)
void qkv_gemm_kernel(const float* __restrict__ X,
                     const float* __restrict__ Wq, const float* __restrict__ bq,
                     const float* __restrict__ Wk, const float* __restrict__ bk,
                     const float* __restrict__ Wv, const float* __restrict__ bv)
{
    const float* W    = (blockIdx.z == 0) ? Wq : (blockIdx.z == 1) ? Wk : Wv;
    const float* bias = (blockIdx.z == 0) ? bq : (blockIdx.z == 1) ? bk : bv;
    float*       dst  = (blockIdx.z == 0) ? g_Q : (blockIdx.z == 1) ? g_K : g_V;

    float acc[8][8];
    gemm_tile_body(X, W, acc);

    const int tid = threadIdx.x;
    const int mb  = blockIdx.y * BM + (tid >> 4) * 8;
    const int nb  = blockIdx.x * BN + (tid & 15) * 8;

    #pragma unroll
    for (int i = 0; i < 8; i++) {
        int m = mb + i;
        int b = m >> 11;        // m / 2048
        int t = m & 2047;
        #pragma unroll
        for (int j = 0; j < 8; j++) {
            int n = nb + j;
            int h = n >> 6;
            int d = n & 63;
            dst[(((size_t)(b * NUM_HEADS + h)) * TSEQ + t) * HEAD_DIM + d] =
                acc[i][j] + bias[n];
        }
    }
}

// ---------------------------------------------------------------------------
// Output projection: g_AO @ Wo + bo -> out (row-major B,T,C)
// grid = (8, 32, 1), block = 256
// ---------------------------------------------------------------------------
__global__ __launch_bounds__(256)
void out_gemm_kernel(const float* __restrict__ Wo, const float* __restrict__ bo,
                     float* __restrict__ out)
{
    float acc[8][8];
    gemm_tile_body(g_AO, Wo, acc);

    const int tid = threadIdx.x;
    const int mb  = blockIdx.y * BM + (tid >> 4) * 8;
    const int nb  = blockIdx.x * BN + (tid & 15) * 8;

    #pragma unroll
    for (int i = 0; i < 8; i++) {
        #pragma unroll
        for (int j = 0; j < 8; j++) {
            out[(size_t)(mb + i) * D_MODEL + (nb + j)] = acc[i][j] + bo[nb + j];
        }
    }
}

// ---------------------------------------------------------------------------
// Attention. One thread per query. Allowed keys for query i:
//   j in [max(0, (blk(i)-1)*128), i]   (block-sparse dominates window+causal)
// ALiBi: score = qk/8 + slope_h * (i - j). Analytic shift slope*(i - j_lo)
// (per-query constant, cancels in softmax) keeps exp() in-range with no
// online-max bookkeeping.
// grid = (16 qblocks, 16 heads, 2 batch), block = 128
// ---------------------------------------------------------------------------
__global__ __launch_bounds__(128)
void attn_kernel(float* __restrict__ attn_out, int store_attn)
{
    const int qb = blockIdx.x;
    const int h  = blockIdx.y;
    const int b  = blockIdx.z;
    const int i  = qb * QBLK + threadIdx.x;
    const int j_lo = (qb == 0) ? 0 : (qb - 1) * QBLK;
    const int nk   = (qb == 0) ? QBLK : 2 * QBLK;

    const size_t bh = (size_t)(b * NUM_HEADS + h);
    const float* qp = g_Q + (bh * TSEQ + i) * HEAD_DIM;
    const float* kb = g_K + (bh * TSEQ + j_lo) * HEAD_DIM;
    const float* vb = g_V + (bh * TSEQ + j_lo) * HEAD_DIM;

    float4 q[16];
    #pragma unroll
    for (int u = 0; u < 16; u++) q[u] = ((const float4*)qp)[u];

    const float slope = exp2f(-0.5f * (float)(h + 1));   // 2^(-8*(h+1)/16)

    float4 o[16];
    #pragma unroll
    for (int u = 0; u < 16; u++) o[u] = make_float4(0.f, 0.f, 0.f, 0.f);
    float l = 0.0f;

    for (int jj = 0; jj < nk; jj++) {
        const float4* kr = (const float4*)(kb + (size_t)jj * HEAD_DIM);
        float s0 = 0.f, s1 = 0.f, s2 = 0.f, s3 = 0.f;
        #pragma unroll
        for (int u = 0; u < 16; u++) {
            float4 kv = kr[u];
            s0 = fmaf(q[u].x, kv.x, s0);
            s1 = fmaf(q[u].y, kv.y, s1);
            s2 = fmaf(q[u].z, kv.z, s2);
            s3 = fmaf(q[u].w, kv.w, s3);
        }
        const int j = j_lo + jj;
        // shifted score: qk*0.125 + slope*(j_lo - j)
        float s = ((s0 + s1) + (s2 + s3)) * 0.125f - slope * (float)jj;
        float p = (j <= i) ? __expf(s) : 0.0f;
        l += p;
        const float4* vr = (const float4*)(vb + (size_t)jj * HEAD_DIM);
        #pragma unroll
        for (int u = 0; u < 16; u++) {
            float4 vv = vr[u];
            o[u].x = fmaf(p, vv.x, o[u].x);
            o[u].y = fmaf(p, vv.y, o[u].y);
            o[u].z = fmaf(p, vv.z, o[u].z);
            o[u].w = fmaf(p, vv.w, o[u].w);
        }
    }

    const float inv = 1.0f / l;
    // store in (B,T,C) layout for the output projection
    float* op = g_AO + ((size_t)(b * TSEQ + i)) * D_MODEL + h * HEAD_DIM;
    #pragma unroll
    for (int u = 0; u < 16; u++) {
        float4 ov = o[u];
        ov.x *= inv; ov.y *= inv; ov.z *= inv; ov.w *= inv;
        ((float4*)op)[u] = ov;
    }

    if (store_attn) {
        float* arow = attn_out + (bh * TSEQ + i) * (size_t)TSEQ;
        for (int jj = 0; jj < nk; jj++) {
            const int j = j_lo + jj;
            if (j > i) break;
            const float4* kr = (const float4*)(kb + (size_t)jj * HEAD_DIM);
            float s0 = 0.f, s1 = 0.f, s2 = 0.f, s3 = 0.f;
            #pragma unroll
            for (int u = 0; u < 16; u++) {
                float4 kv = kr[u];
                s0 = fmaf(q[u].x, kv.x, s0);
                s1 = fmaf(q[u].y, kv.y, s1);
                s2 = fmaf(q[u].z, kv.z, s2);
                s3 = fmaf(q[u].w, kv.w, s3);
            }
            float s = ((s0 + s1) + (s2 + s3)) * 0.125f - slope * (float)jj;
            arow[j] = __expf(s) * inv;
        }
    }
}

// ---------------------------------------------------------------------------
// Launch
// ---------------------------------------------------------------------------
extern "C" void kernel_launch(void* const* d_in, const int* in_sizes, int n_in,
                              void* d_out, int out_size)
{
    const float* x  = (const float*)d_in[0];
    const float* Wq = (const float*)d_in[1];
    const float* bq = (const float*)d_in[2];
    const float* Wk = (const float*)d_in[3];
    const float* bk = (const float*)d_in[4];
    const float* Wv = (const float*)d_in[5];
    const float* bv = (const float*)d_in[6];
    const float* Wo = (const float*)d_in[7];
    const float* bo = (const float*)d_in[8];
    float* out = (float*)d_out;

    const long long out_elems  = (long long)MROWS * D_MODEL;                 // 4,194,304
    const long long attn_elems = (long long)BSZ * NUM_HEADS * TSEQ * TSEQ;   // 134,217,728
    const int store_attn = ((long long)out_size >= out_elems + attn_elems) ? 1 : 0;

    // 1) QKV projections
    dim3 gq(D_MODEL / BN, MROWS / BM, 3);
    qkv_gemm_kernel<<<gq, 256>>>(x, Wq, bq, Wk, bk, Wv, bv);

    // 2) (optional) zero the attention-probability plane; mask zeros stay exact
    float* attn_ptr = out + out_elems;
    if (store_attn)
        cudaMemsetAsync(attn_ptr, 0, (size_t)attn_elems * sizeof(float));

    // 3) fused masked attention (+ optional sparse attn-band store)
    dim3 ga(TSEQ / QBLK, NUM_HEADS, BSZ);
    attn_kernel<<<ga, 128>>>(attn_ptr, store_attn);

    // 4) output projection
    dim3 go(D_MODEL / BN, MROWS / BM, 1);
    out_gemm_kernel<<<go, 256>>>(Wo, bo, out);
}

// round 2
// speedup vs baseline: 1.8759x; 1.8759x over previous
#include <cuda_runtime.h>
#include <math.h>

// ---------------------------------------------------------------------------
// Problem constants
// ---------------------------------------------------------------------------
#define D_MODEL   1024
#define NUM_HEADS 16
#define HEAD_DIM  64
#define BSZ       2
#define TSEQ      2048
#define MROWS     (BSZ * TSEQ)      // 4096
#define QBLK      128               // block-sparse block size
#define NROWS_ATT (BSZ * NUM_HEADS * TSEQ)   // 65536

// ---------------------------------------------------------------------------
// Scratch (device globals: allocation-free per harness rules)
// ---------------------------------------------------------------------------
__device__ float g_Q[(size_t)BSZ * NUM_HEADS * TSEQ * HEAD_DIM];   // [B,H,T,hd]
__device__ float g_K[(size_t)BSZ * NUM_HEADS * TSEQ * HEAD_DIM];
__device__ float g_V[(size_t)BSZ * NUM_HEADS * TSEQ * HEAD_DIM];
__device__ float g_AO[(size_t)MROWS * D_MODEL];                    // [B,T,C]
__device__ float g_InvL[NROWS_ATT];                                // 1/softmax-denominator

// ---------------------------------------------------------------------------
// Double-buffered fp32 GEMM body: C_tile(128x128) = A(4096x1024)*W(1024x1024)
// 256 threads, 8x8 micro-tile, BK=8, smem+register double buffering.
// ---------------------------------------------------------------------------
#define BM 128
#define BN 128
#define BK 8

__device__ __forceinline__ void gemm_tile_body(const float* __restrict__ A,
                                               const float* __restrict__ W,
                                               float acc[8][8])
{
    __shared__ float As[2][BK][BM];
    __shared__ float Bs[2][BK][BN];

    const int tid  = threadIdx.x;
    const int m0   = blockIdx.y * BM;
    const int n0   = blockIdx.x * BN;
    const int arow = tid >> 1;           // 0..127
    const int acol = (tid & 1) * 4;      // 0 or 4
    const int brow = tid >> 5;           // 0..7
    const int bcol = (tid & 31) * 4;     // 0..124
    const int tr   = (tid >> 4) * 8;     // 0..120
    const int tc   = (tid & 15) * 8;     // 0..120

    const float* Aptr = A + (size_t)(m0 + arow) * 1024 + acol;
    const float* Wptr = W + (size_t)brow * 1024 + n0 + bcol;

    #pragma unroll
    for (int i = 0; i < 8; i++)
        #pragma unroll
        for (int j = 0; j < 8; j++)
            acc[i][j] = 0.0f;

    // prologue: load tile k0=0 into buffer 0
    float4 pa = *(const float4*)(Aptr);
    float4 pb = *(const float4*)(Wptr);
    As[0][acol + 0][arow] = pa.x;
    As[0][acol + 1][arow] = pa.y;
    As[0][acol + 2][arow] = pa.z;
    As[0][acol + 3][arow] = pa.w;
    *(float4*)&Bs[0][brow][bcol] = pb;
    __syncthreads();

    int buf = 0;
    for (int k0 = 0; k0 < 1024; k0 += BK) {
        const bool more = (k0 + BK) < 1024;
        if (more) {
            pa = *(const float4*)(Aptr + k0 + BK);
            pb = *(const float4*)(Wptr + (size_t)(k0 + BK) * 1024);
        }

        // register-double-buffered compute over current smem buffer
        float4 a0 = *(const float4*)&As[buf][0][tr];
        float4 a1 = *(const float4*)&As[buf][0][tr + 4];
        float4 b0 = *(const float4*)&Bs[buf][0][tc];
        float4 b1 = *(const float4*)&Bs[buf][0][tc + 4];
        #pragma unroll
        for (int kk = 0; kk < BK; kk++) {
            float4 na0, na1, nb0, nb1;
            if (kk < BK - 1) {
                na0 = *(const float4*)&As[buf][kk + 1][tr];
                na1 = *(const float4*)&As[buf][kk + 1][tr + 4];
                nb0 = *(const float4*)&Bs[buf][kk + 1][tc];
                nb1 = *(const float4*)&Bs[buf][kk + 1][tc + 4];
            }
            float ra[8] = {a0.x, a0.y, a0.z, a0.w, a1.x, a1.y, a1.z, a1.w};
            float rb[8] = {b0.x, b0.y, b0.z, b0.w, b1.x, b1.y, b1.z, b1.w};
            #pragma unroll
            for (int i = 0; i < 8; i++)
                #pragma unroll
                for (int j = 0; j < 8; j++)
                    acc[i][j] = fmaf(ra[i], rb[j], acc[i][j]);
            if (kk < BK - 1) { a0 = na0; a1 = na1; b0 = nb0; b1 = nb1; }
        }

        if (more) {
            As[buf ^ 1][acol + 0][arow] = pa.x;
            As[buf ^ 1][acol + 1][arow] = pa.y;
            As[buf ^ 1][acol + 2][arow] = pa.z;
            As[buf ^ 1][acol + 3][arow] = pa.w;
            *(float4*)&Bs[buf ^ 1][brow][bcol] = pb;
        }
        __syncthreads();
        buf ^= 1;
    }
}

// ---------------------------------------------------------------------------
// QKV projection: X @ {Wq,Wk,Wv} + bias -> g_Q/g_K/g_V in [B,H,T,hd] layout.
// ---------------------------------------------------------------------------
__global__ __launch_bounds__(256, 2)
void qkv_gemm_kernel(const float* __restrict__ X,
                     const float* __restrict__ Wq, const float* __restrict__ bq,
                     const float* __restrict__ Wk, const float* __restrict__ bk,
                     const float* __restrict__ Wv, const float* __restrict__ bv)
{
    const float* W    = (blockIdx.z == 0) ? Wq : (blockIdx.z == 1) ? Wk : Wv;
    const float* bias = (blockIdx.z == 0) ? bq : (blockIdx.z == 1) ? bk : bv;
    float*       dst  = (blockIdx.z == 0) ? g_Q : (blockIdx.z == 1) ? g_K : g_V;

    float acc[8][8];
    gemm_tile_body(X, W, acc);

    const int tid = threadIdx.x;
    const int mb  = blockIdx.y * BM + (tid >> 4) * 8;
    const int nb  = blockIdx.x * BN + (tid & 15) * 8;

    #pragma unroll
    for (int i = 0; i < 8; i++) {
        int m = mb + i;
        int b = m >> 11;        // m / 2048
        int t = m & 2047;
        #pragma unroll
        for (int j = 0; j < 8; j++) {
            int n = nb + j;
            int h = n >> 6;
            int d = n & 63;
            dst[(((size_t)(b * NUM_HEADS + h)) * TSEQ + t) * HEAD_DIM + d] =
                acc[i][j] + bias[n];
        }
    }
}

// ---------------------------------------------------------------------------
// Output projection: g_AO @ Wo + bo -> out (row-major B,T,C)
// ---------------------------------------------------------------------------
__global__ __launch_bounds__(256, 2)
void out_gemm_kernel(const float* __restrict__ Wo, const float* __restrict__ bo,
                     float* __restrict__ out)
{
    float acc[8][8];
    gemm_tile_body(g_AO, Wo, acc);

    const int tid = threadIdx.x;
    const int mb  = blockIdx.y * BM + (tid >> 4) * 8;
    const int nb  = blockIdx.x * BN + (tid & 15) * 8;

    #pragma unroll
    for (int i = 0; i < 8; i++) {
        #pragma unroll
        for (int j = 0; j < 8; j++) {
            out[(size_t)(mb + i) * D_MODEL + (nb + j)] = acc[i][j] + bo[nb + j];
        }
    }
}

// ---------------------------------------------------------------------------
// Attention. One thread per query; K/V chunks staged in smem cooperatively.
// Allowed keys for query i: j in [(blk(i)-1)*128 (clamped), i].
// ALiBi shifted score (per-query constant cancels in softmax).
// Writes UNNORMALIZED probabilities to attn_out; scale pass divides later.
// grid = (16 qblocks, 16 heads, 2 batch), block = 128
// ---------------------------------------------------------------------------
#define CHUNK 64

__global__ __launch_bounds__(128)
void attn_kernel(float* __restrict__ attn_out, int store_attn)
{
    __shared__ float sK[CHUNK][HEAD_DIM];
    __shared__ float sV[CHUNK][HEAD_DIM];

    const int tid = threadIdx.x;
    const int qb = blockIdx.x;
    const int h  = blockIdx.y;
    const int b  = blockIdx.z;
    const int i  = qb * QBLK + tid;
    const int j_lo = (qb == 0) ? 0 : (qb - 1) * QBLK;
    const int nk   = (qb == 0) ? QBLK : 2 * QBLK;
    const int warp_imax = i | 31;        // warp-uniform upper query index

    const size_t bh = (size_t)(b * NUM_HEADS + h);
    const float* qp = g_Q + (bh * TSEQ + i) * HEAD_DIM;
    const float4* gK = (const float4*)(g_K + (bh * TSEQ + j_lo) * HEAD_DIM);
    const float4* gV = (const float4*)(g_V + (bh * TSEQ + j_lo) * HEAD_DIM);

    float4 q[16];
    #pragma unroll
    for (int u = 0; u < 16; u++) q[u] = ((const float4*)qp)[u];

    const float slope = exp2f(-0.5f * (float)(h + 1));   // 2^(-8*(h+1)/16)

    float4 o[16];
    #pragma unroll
    for (int u = 0; u < 16; u++) o[u] = make_float4(0.f, 0.f, 0.f, 0.f);
    float l = 0.0f;

    float* arow = attn_out + (bh * TSEQ + i) * (size_t)TSEQ;

    for (int c0 = 0; c0 < nk; c0 += CHUNK) {
        // cooperative chunk load (coalesced float4)
        float4* s4K = (float4*)sK;
        float4* s4V = (float4*)sV;
        const int base = c0 * (HEAD_DIM / 4);
        #pragma unroll
        for (int f = 0; f < CHUNK * (HEAD_DIM / 4); f += 128) {
            s4K[f + tid] = gK[base + f + tid];
            s4V[f + tid] = gV[base + f + tid];
        }
        __syncthreads();

        int lim = warp_imax - j_lo - c0 + 1;   // warp-uniform causal bound
        if (lim > CHUNK) lim = CHUNK;
        for (int jj = 0; jj < lim; jj++) {
            const float4* kr = (const float4*)sK[jj];
            float s0 = 0.f, s1 = 0.f, s2 = 0.f, s3 = 0.f;
            #pragma unroll
            for (int u = 0; u < 16; u++) {
                float4 kv = kr[u];
                s0 = fmaf(q[u].x, kv.x, s0);
                s1 = fmaf(q[u].y, kv.y, s1);
                s2 = fmaf(q[u].z, kv.z, s2);
                s3 = fmaf(q[u].w, kv.w, s3);
            }
            const int j = j_lo + c0 + jj;
            float s = ((s0 + s1) + (s2 + s3)) * 0.125f - slope * (float)(c0 + jj);
            float p = (j <= i) ? __expf(s) : 0.0f;
            l += p;
            if (store_attn && (j <= i)) arow[j] = p;   // unnormalized
            const float4* vr = (const float4*)sV[jj];
            #pragma unroll
            for (int u = 0; u < 16; u++) {
                float4 vv = vr[u];
                o[u].x = fmaf(p, vv.x, o[u].x);
                o[u].y = fmaf(p, vv.y, o[u].y);
                o[u].z = fmaf(p, vv.z, o[u].z);
                o[u].w = fmaf(p, vv.w, o[u].w);
            }
        }
        __syncthreads();
    }

    const float inv = 1.0f / l;
    g_InvL[bh * TSEQ + i] = inv;

    // store normalized context in (B,T,C) layout for the output projection
    float* op = g_AO + ((size_t)(b * TSEQ + i)) * D_MODEL + h * HEAD_DIM;
    #pragma unroll
    for (int u = 0; u < 16; u++) {
        float4 ov = o[u];
        ov.x *= inv; ov.y *= inv; ov.z *= inv; ov.w *= inv;
        ((float4*)op)[u] = ov;
    }
}

// ---------------------------------------------------------------------------
// Scale pass: normalize the sparse attention band in-place.
// One warp per (b,h,i) row.
// ---------------------------------------------------------------------------
__global__ __launch_bounds__(256)
void scale_attn_kernel(float* __restrict__ attn)
{
    const int warp_g = (blockIdx.x * blockDim.x + threadIdx.x) >> 5;
    if (warp_g >= NROWS_ATT) return;
    const int lane = threadIdx.x & 31;
    const int i  = warp_g & (TSEQ - 1);
    const int qb = i >> 7;
    const int j_lo = (qb == 0) ? 0 : (qb - 1) * QBLK;
    const float inv = g_InvL[warp_g];
    float* arow = attn + (size_t)warp_g * TSEQ;
    for (int j = j_lo + lane; j <= i; j += 32)
        arow[j] *= inv;
}

// ---------------------------------------------------------------------------
// Launch
// ---------------------------------------------------------------------------
extern "C" void kernel_launch(void* const* d_in, const int* in_sizes, int n_in,
                              void* d_out, int out_size)
{
    const float* x  = (const float*)d_in[0];
    const float* Wq = (const float*)d_in[1];
    const float* bq = (const float*)d_in[2];
    const float* Wk = (const float*)d_in[3];
    const float* bk = (const float*)d_in[4];
    const float* Wv = (const float*)d_in[5];
    const float* bv = (const float*)d_in[6];
    const float* Wo = (const float*)d_in[7];
    const float* bo = (const float*)d_in[8];
    float* out = (float*)d_out;

    const long long out_elems  = (long long)MROWS * D_MODEL;                 // 4,194,304
    const long long attn_elems = (long long)BSZ * NUM_HEADS * TSEQ * TSEQ;   // 134,217,728
    const int store_attn = ((long long)out_size >= out_elems + attn_elems) ? 1 : 0;

    // 1) QKV projections
    dim3 gq(D_MODEL / BN, MROWS / BM, 3);
    qkv_gemm_kernel<<<gq, 256>>>(x, Wq, bq, Wk, bk, Wv, bv);

    // 2) (optional) zero the attention-probability plane; masked entries stay 0
    float* attn_ptr = out + out_elems;
    if (store_attn)
        cudaMemsetAsync(attn_ptr, 0, (size_t)attn_elems * sizeof(float));

    // 3) fused masked attention (writes unnormalized band if store_attn)
    dim3 ga(TSEQ / QBLK, NUM_HEADS, BSZ);
    attn_kernel<<<ga, 128>>>(attn_ptr, store_attn);

    // 4) normalize the band
    if (store_attn) {
        int warps = NROWS_ATT;
        int blocks = (warps * 32 + 255) / 256;
        scale_attn_kernel<<<blocks, 256>>>(attn_ptr);
    }

    // 5) output projection
    dim3 go(D_MODEL / BN, MROWS / BM, 1);
    out_gemm_kernel<<<go, 256>>>(Wo, bo, out);
}

// round 3
// speedup vs baseline: 2.2743x; 1.2124x over previous
#include <cuda_runtime.h>
#include <math.h>
#include <stdint.h>

// ---------------------------------------------------------------------------
// Problem constants
// ---------------------------------------------------------------------------
#define D_MODEL   1024
#define NUM_HEADS 16
#define HEAD_DIM  64
#define BSZ       2
#define TSEQ      2048
#define MROWS     (BSZ * TSEQ)      // 4096
#define QBLK      128               // block-sparse block size
#define NROWS_ATT (BSZ * NUM_HEADS * TSEQ)   // 65536

// ---------------------------------------------------------------------------
// Scratch (device globals: allocation-free per harness rules)
// ---------------------------------------------------------------------------
__device__ float g_Q[(size_t)BSZ * NUM_HEADS * TSEQ * HEAD_DIM];   // [B,H,T,hd]
__device__ float g_K[(size_t)BSZ * NUM_HEADS * TSEQ * HEAD_DIM];
__device__ float g_V[(size_t)BSZ * NUM_HEADS * TSEQ * HEAD_DIM];
__device__ float g_AO[(size_t)MROWS * D_MODEL];                    // [B,T,C]
__device__ float g_InvL[NROWS_ATT];                                // 1/softmax denom

// ---------------------------------------------------------------------------
// tf32 helpers
// ---------------------------------------------------------------------------
__device__ __forceinline__ uint32_t f2tf32(float x) {
    uint32_t r;
    asm("cvt.rna.tf32.f32 %0, %1;" : "=r"(r) : "f"(x));
    return r;
}

#define MMA_TF32(c, a0, a1, a2, a3, b0, b1)                                   \
    asm volatile(                                                             \
        "mma.sync.aligned.m16n8k8.row.col.f32.tf32.tf32.f32 "                 \
        "{%0,%1,%2,%3}, {%4,%5,%6,%7}, {%8,%9}, {%0,%1,%2,%3};\n"            \
        : "+f"((c)[0]), "+f"((c)[1]), "+f"((c)[2]), "+f"((c)[3])              \
        : "r"(a0), "r"(a1), "r"(a2), "r"(a3), "r"(b0), "r"(b1))

// ---------------------------------------------------------------------------
// 3xTF32 tensor-core GEMM body:
//   C_tile(128x128) = A(Mx1024) * W(1024x1024), fp32-equivalent accuracy via
//   hi/lo mantissa split (drops only the a_lo*b_lo term ~2e-7 relative).
// 256 threads = 8 warps (4x2 warp grid, 32x64 warp tile), BK=8, double-buffered.
// Smem planes stride 136: fragment reads provably bank-conflict-free.
// ---------------------------------------------------------------------------
#define BM 128
#define BN 128
#define BK 8
#define SSTR 136

__device__ __forceinline__ void gemm3x_body(const float* __restrict__ A,
                                            const float* __restrict__ W,
                                            float acc[2][8][4])
{
    __shared__ uint32_t AsH[2][BK][SSTR];
    __shared__ uint32_t AsL[2][BK][SSTR];
    __shared__ uint32_t BsH[2][BK][SSTR];
    __shared__ uint32_t BsL[2][BK][SSTR];

    const int tid   = threadIdx.x;
    const int lane  = tid & 31;
    const int wid   = tid >> 5;
    const int grp   = lane >> 2;          // 0..7
    const int kcol  = lane & 3;           // 0..3
    const int wm    = (wid >> 1) * 32;    // warp row offset
    const int wn    = (wid & 1) * 64;     // warp col offset

    const int m0   = blockIdx.y * BM;
    const int n0   = blockIdx.x * BN;
    const int arow = tid >> 1;            // 0..127
    const int acol = (tid & 1) * 4;       // 0 or 4
    const int brow = tid >> 5;            // 0..7
    const int bcol = (tid & 31) * 4;      // 0..124

    const float* Aptr = A + (size_t)(m0 + arow) * 1024 + acol;
    const float* Wptr = W + (size_t)brow * 1024 + n0 + bcol;

    #pragma unroll
    for (int f = 0; f < 2; f++)
        #pragma unroll
        for (int g = 0; g < 8; g++)
            #pragma unroll
            for (int c = 0; c < 4; c++)
                acc[f][g][c] = 0.0f;

    // prologue: k0 = 0 into buffer 0
    float4 pa = *(const float4*)(Aptr);
    float4 pb = *(const float4*)(Wptr);
    {
        float av[4] = {pa.x, pa.y, pa.z, pa.w};
        float bv[4] = {pb.x, pb.y, pb.z, pb.w};
        #pragma unroll
        for (int c = 0; c < 4; c++) {
            uint32_t h = f2tf32(av[c]);
            AsH[0][acol + c][arow] = h;
            AsL[0][acol + c][arow] = f2tf32(av[c] - __uint_as_float(h));
            uint32_t hb = f2tf32(bv[c]);
            BsH[0][brow][bcol + c] = hb;
            BsL[0][brow][bcol + c] = f2tf32(bv[c] - __uint_as_float(hb));
        }
    }
    __syncthreads();

    int buf = 0;
    for (int k0 = 0; k0 < 1024; k0 += BK) {
        const bool more = (k0 + BK) < 1024;
        if (more) {
            pa = *(const float4*)(Aptr + k0 + BK);
            pb = *(const float4*)(Wptr + (size_t)(k0 + BK) * 1024);
        }

        // ---- A fragments (hi+lo) ----
        uint32_t aH[2][4], aL[2][4];
        #pragma unroll
        for (int f = 0; f < 2; f++) {
            int r0 = wm + f * 16 + grp;
            aH[f][0] = AsH[buf][kcol][r0];
            aH[f][1] = AsH[buf][kcol][r0 + 8];
            aH[f][2] = AsH[buf][kcol + 4][r0];
            aH[f][3] = AsH[buf][kcol + 4][r0 + 8];
            aL[f][0] = AsL[buf][kcol][r0];
            aL[f][1] = AsL[buf][kcol][r0 + 8];
            aL[f][2] = AsL[buf][kcol + 4][r0];
            aL[f][3] = AsL[buf][kcol + 4][r0 + 8];
        }

        // ---- per n-fragment: 3-pass MMA ----
        #pragma unroll
        for (int g = 0; g < 8; g++) {
            int n = wn + g * 8 + grp;
            uint32_t bH0 = BsH[buf][kcol][n];
            uint32_t bH1 = BsH[buf][kcol + 4][n];
            uint32_t bL0 = BsL[buf][kcol][n];
            uint32_t bL1 = BsL[buf][kcol + 4][n];
            #pragma unroll
            for (int f = 0; f < 2; f++) {
                MMA_TF32(acc[f][g], aH[f][0], aH[f][1], aH[f][2], aH[f][3], bH0, bH1);
                MMA_TF32(acc[f][g], aL[f][0], aL[f][1], aL[f][2], aL[f][3], bH0, bH1);
                MMA_TF32(acc[f][g], aH[f][0], aH[f][1], aH[f][2], aH[f][3], bL0, bL1);
            }
        }

        if (more) {
            float av[4] = {pa.x, pa.y, pa.z, pa.w};
            float bv[4] = {pb.x, pb.y, pb.z, pb.w};
            #pragma unroll
            for (int c = 0; c < 4; c++) {
                uint32_t h = f2tf32(av[c]);
                AsH[buf ^ 1][acol + c][arow] = h;
                AsL[buf ^ 1][acol + c][arow] = f2tf32(av[c] - __uint_as_float(h));
                uint32_t hb = f2tf32(bv[c]);
                BsH[buf ^ 1][brow][bcol + c] = hb;
                BsL[buf ^ 1][brow][bcol + c] = f2tf32(bv[c] - __uint_as_float(hb));
            }
        }
        __syncthreads();
        buf ^= 1;
    }
}

// ---------------------------------------------------------------------------
// QKV projection: X @ {Wq,Wk,Wv} + bias -> g_Q/g_K/g_V in [B,H,T,hd] layout.
// ---------------------------------------------------------------------------
__global__ __launch_bounds__(256, 2)
void qkv_gemm_kernel(const float* __restrict__ X,
                     const float* __restrict__ Wq, const float* __restrict__ bq,
                     const float* __restrict__ Wk, const float* __restrict__ bk,
                     const float* __restrict__ Wv, const float* __restrict__ bv)
{
    const float* W    = (blockIdx.z == 0) ? Wq : (blockIdx.z == 1) ? Wk : Wv;
    const float* bias = (blockIdx.z == 0) ? bq : (blockIdx.z == 1) ? bk : bv;
    float*       dst  = (blockIdx.z == 0) ? g_Q : (blockIdx.z == 1) ? g_K : g_V;

    float acc[2][8][4];
    gemm3x_body(X, W, acc);

    const int lane = threadIdx.x & 31;
    const int wid  = threadIdx.x >> 5;
    const int grp  = lane >> 2;
    const int qd   = lane & 3;
    const int mb   = blockIdx.y * BM + (wid >> 1) * 32;
    const int nb   = blockIdx.x * BN + (wid & 1) * 64;

    #pragma unroll
    for (int f = 0; f < 2; f++) {
        #pragma unroll
        for (int g = 0; g < 8; g++) {
            #pragma unroll
            for (int c = 0; c < 4; c++) {
                int m = mb + f * 16 + grp + (c >> 1) * 8;
                int n = nb + g * 8 + 2 * qd + (c & 1);
                int b = m >> 11;
                int t = m & 2047;
                int h = n >> 6;
                int d = n & 63;
                dst[(((size_t)(b * NUM_HEADS + h)) * TSEQ + t) * HEAD_DIM + d] =
                    acc[f][g][c] + bias[n];
            }
        }
    }
}

// ---------------------------------------------------------------------------
// Output projection: g_AO @ Wo + bo -> out (row-major B,T,C)
// ---------------------------------------------------------------------------
__global__ __launch_bounds__(256, 2)
void out_gemm_kernel(const float* __restrict__ Wo, const float* __restrict__ bo,
                     float* __restrict__ out)
{
    float acc[2][8][4];
    gemm3x_body(g_AO, Wo, acc);

    const int lane = threadIdx.x & 31;
    const int wid  = threadIdx.x >> 5;
    const int grp  = lane >> 2;
    const int qd   = lane & 3;
    const int mb   = blockIdx.y * BM + (wid >> 1) * 32;
    const int nb   = blockIdx.x * BN + (wid & 1) * 64;

    #pragma unroll
    for (int f = 0; f < 2; f++) {
        #pragma unroll
        for (int g = 0; g < 8; g++) {
            #pragma unroll
            for (int c = 0; c < 4; c++) {
                int m = mb + f * 16 + grp + (c >> 1) * 8;
                int n = nb + g * 8 + 2 * qd + (c & 1);
                out[(size_t)m * D_MODEL + n] = acc[f][g][c] + bo[n];
            }
        }
    }
}

// ---------------------------------------------------------------------------
// Attention. One thread per query; K/V chunks staged in smem cooperatively.
// Allowed keys for query i: j in [(blk(i)-1)*128 (clamped), i].
// ALiBi shifted score (per-query constant cancels in softmax).
// Writes UNNORMALIZED probabilities to attn_out; scale pass divides later.
// grid = (16 qblocks, 16 heads, 2 batch), block = 128
// ---------------------------------------------------------------------------
#define CHUNK 64

__global__ __launch_bounds__(128)
void attn_kernel(float* __restrict__ attn_out, int store_attn)
{
    __shared__ float sK[CHUNK][HEAD_DIM];
    __shared__ float sV[CHUNK][HEAD_DIM];

    const int tid = threadIdx.x;
    const int qb = blockIdx.x;
    const int h  = blockIdx.y;
    const int b  = blockIdx.z;
    const int i  = qb * QBLK + tid;
    const int j_lo = (qb == 0) ? 0 : (qb - 1) * QBLK;
    const int nk   = (qb == 0) ? QBLK : 2 * QBLK;
    const int warp_imax = i | 31;        // warp-uniform upper query index

    const size_t bh = (size_t)(b * NUM_HEADS + h);
    const float* qp = g_Q + (bh * TSEQ + i) * HEAD_DIM;
    const float4* gK = (const float4*)(g_K + (bh * TSEQ + j_lo) * HEAD_DIM);
    const float4* gV = (const float4*)(g_V + (bh * TSEQ + j_lo) * HEAD_DIM);

    float4 q[16];
    #pragma unroll
    for (int u = 0; u < 16; u++) q[u] = ((const float4*)qp)[u];

    const float slope = exp2f(-0.5f * (float)(h + 1));   // 2^(-8*(h+1)/16)

    float4 o[16];
    #pragma unroll
    for (int u = 0; u < 16; u++) o[u] = make_float4(0.f, 0.f, 0.f, 0.f);
    float l = 0.0f;

    float* arow = attn_out + (bh * TSEQ + i) * (size_t)TSEQ;

    for (int c0 = 0; c0 < nk; c0 += CHUNK) {
        float4* s4K = (float4*)sK;
        float4* s4V = (float4*)sV;
        const int base = c0 * (HEAD_DIM / 4);
        #pragma unroll
        for (int f = 0; f < CHUNK * (HEAD_DIM / 4); f += 128) {
            s4K[f + tid] = gK[base + f + tid];
            s4V[f + tid] = gV[base + f + tid];
        }
        __syncthreads();

        int lim = warp_imax - j_lo - c0 + 1;   // warp-uniform causal bound
        if (lim > CHUNK) lim = CHUNK;
        for (int jj = 0; jj < lim; jj++) {
            const float4* kr = (const float4*)sK[jj];
            float s0 = 0.f, s1 = 0.f, s2 = 0.f, s3 = 0.f;
            #pragma unroll
            for (int u = 0; u < 16; u++) {
                float4 kv = kr[u];
                s0 = fmaf(q[u].x, kv.x, s0);
                s1 = fmaf(q[u].y, kv.y, s1);
                s2 = fmaf(q[u].z, kv.z, s2);
                s3 = fmaf(q[u].w, kv.w, s3);
            }
            const int j = j_lo + c0 + jj;
            float s = ((s0 + s1) + (s2 + s3)) * 0.125f - slope * (float)(c0 + jj);
            float p = (j <= i) ? __expf(s) : 0.0f;
            l += p;
            if (store_attn && (j <= i)) arow[j] = p;   // unnormalized
            const float4* vr = (const float4*)sV[jj];
            #pragma unroll
            for (int u = 0; u < 16; u++) {
                float4 vv = vr[u];
                o[u].x = fmaf(p, vv.x, o[u].x);
                o[u].y = fmaf(p, vv.y, o[u].y);
                o[u].z = fmaf(p, vv.z, o[u].z);
                o[u].w = fmaf(p, vv.w, o[u].w);
            }
        }
        __syncthreads();
    }

    const float inv = 1.0f / l;
    g_InvL[bh * TSEQ + i] = inv;

    float* op = g_AO + ((size_t)(b * TSEQ + i)) * D_MODEL + h * HEAD_DIM;
    #pragma unroll
    for (int u = 0; u < 16; u++) {
        float4 ov = o[u];
        ov.x *= inv; ov.y *= inv; ov.z *= inv; ov.w *= inv;
        ((float4*)op)[u] = ov;
    }
}

// ---------------------------------------------------------------------------
// Scale pass: normalize the sparse attention band in-place.
// ---------------------------------------------------------------------------
__global__ __launch_bounds__(256)
void scale_attn_kernel(float* __restrict__ attn)
{
    const int warp_g = (blockIdx.x * blockDim.x + threadIdx.x) >> 5;
    if (warp_g >= NROWS_ATT) return;
    const int lane = threadIdx.x & 31;
    const int i  = warp_g & (TSEQ - 1);
    const int qb = i >> 7;
    const int j_lo = (qb == 0) ? 0 : (qb - 1) * QBLK;
    const float inv = g_InvL[warp_g];
    float* arow = attn + (size_t)warp_g * TSEQ;
    for (int j = j_lo + lane; j <= i; j += 32)
        arow[j] *= inv;
}

// ---------------------------------------------------------------------------
// Launch
// ---------------------------------------------------------------------------
extern "C" void kernel_launch(void* const* d_in, const int* in_sizes, int n_in,
                              void* d_out, int out_size)
{
    const float* x  = (const float*)d_in[0];
    const float* Wq = (const float*)d_in[1];
    const float* bq = (const float*)d_in[2];
    const float* Wk = (const float*)d_in[3];
    const float* bk = (const float*)d_in[4];
    const float* Wv = (const float*)d_in[5];
    const float* bv = (const float*)d_in[6];
    const float* Wo = (const float*)d_in[7];
    const float* bo = (const float*)d_in[8];
    float* out = (float*)d_out;

    const long long out_elems  = (long long)MROWS * D_MODEL;                 // 4,194,304
    const long long attn_elems = (long long)BSZ * NUM_HEADS * TSEQ * TSEQ;   // 134,217,728
    const int store_attn = ((long long)out_size >= out_elems + attn_elems) ? 1 : 0;

    // 1) QKV projections (tensor-core 3xTF32)
    dim3 gq(D_MODEL / BN, MROWS / BM, 3);
    qkv_gemm_kernel<<<gq, 256>>>(x, Wq, bq, Wk, bk, Wv, bv);

    // 2) (optional) zero the attention plane; masked entries stay 0
    float* attn_ptr = out + out_elems;
    if (store_attn)
        cudaMemsetAsync(attn_ptr, 0, (size_t)attn_elems * sizeof(float));

    // 3) fused masked attention (writes unnormalized band if store_attn)
    dim3 ga(TSEQ / QBLK, NUM_HEADS, BSZ);
    attn_kernel<<<ga, 128>>>(attn_ptr, store_attn);

    // 4) normalize the band
    if (store_attn) {
        int blocks = (NROWS_ATT * 32 + 255) / 256;
        scale_attn_kernel<<<blocks, 256>>>(attn_ptr);
    }

    // 5) output projection (tensor-core 3xTF32)
    dim3 go(D_MODEL / BN, MROWS / BM, 1);
    out_gemm_kernel<<<go, 256>>>(Wo, bo, out);
}